// round 8
// baseline (speedup 1.0000x reference)
#include <cuda_runtime.h>
#include <cuda_fp16.h>
#include <cstdint>
#include <math.h>

#define V 33
#define V3 (V*V*V)          // 35937
#define BATCH 2
#define HW 2048
#define NPIX (HW*HW)

// ---------------- scratch (static device globals; no allocation) -------------
__device__ float  g_rs[BATCH*3*256*256];
__device__ float  g_a1[BATCH*16*128*128];
__device__ float  g_a2[BATCH*32*64*64];
__device__ float  g_a3[BATCH*64*32*32];
__device__ float  g_a4[BATCH*128*16*16];
__device__ float  g_a5[BATCH*128*8*8];
__device__ float  g_wts[BATCH*3];
__device__ float  g_vert[BATCH*3*V];
__device__ float4 g_tbl[BATCH*3*256];   // inverse lookup table {idx, v0, v1, inv}

// quad-packed fp16 LUT: entry(flat=(ib,ig,ir)) holds the 4 (dg,dr) corners
struct alignas(32) Lut4 { uint4 rg; uint2 bb; uint2 pad; };
__device__ Lut4 g_lut4[BATCH*V3];

__device__ __forceinline__ unsigned int h2u(__half2 h) {
    return *reinterpret_cast<unsigned int*>(&h);
}

// ---------------- stage 1: bilinear 2048 -> 256 (scale exactly 8) ------------
__global__ void resize_k(const float* __restrict__ img) {
    int i = blockIdx.x * blockDim.x + threadIdx.x;
    if (i >= BATCH*3*256*256) return;
    int ox = i & 255;
    int oy = (i >> 8) & 255;
    int pc = i >> 16;                       // b*3 + c
    const float* p = img + (size_t)pc * NPIX;
    int iy = oy*8 + 3, ix = ox*8 + 3;
    float p00 = p[(size_t)iy*HW + ix];
    float p01 = p[(size_t)iy*HW + ix + 1];
    float p10 = p[(size_t)(iy+1)*HW + ix];
    float p11 = p[(size_t)(iy+1)*HW + ix + 1];
    float r0 = 0.5f*p00 + 0.5f*p10;
    float r1 = 0.5f*p01 + 0.5f*p11;
    g_rs[i] = 0.5f*r0 + 0.5f*r1;
}

// ------- thread-per-output conv (shallow CI), weights in smem (R5 style) -----
template<int CI, int CO, int HIN, int TPB>
__global__ __launch_bounds__(TPB) void conv_k(const float* __restrict__ in,
                       const float* __restrict__ w,
                       const float* __restrict__ bias, float* __restrict__ out) {
    const int HO = HIN / 2;
    const int PLANE = HO * HO;
    const int BPP = PLANE / TPB;
    int blk  = blockIdx.x;
    int pix  = (blk % BPP) * TPB + threadIdx.x;
    int co   = (blk / BPP) % CO;
    int b    = blk / (BPP * CO);

    __shared__ float sw[CI*9];
    for (int i = threadIdx.x; i < CI*9; i += TPB) sw[i] = w[(size_t)co*CI*9 + i];
    __syncthreads();

    int ox = pix % HO;
    int oy = pix / HO;
    float acc = bias[co];
    const float* ib = in + (size_t)b*CI*HIN*HIN;
    int iy0 = oy*2 - 1, ix0 = ox*2 - 1;
    if (iy0 >= 0 && ix0 >= 0) {
        const float* ip = ib + (size_t)iy0*HIN + ix0;
        const float* wp = sw;
        for (int ci = 0; ci < CI; ci++) {
            acc += ip[0]      *wp[0] + ip[1]      *wp[1] + ip[2]      *wp[2];
            acc += ip[HIN]    *wp[3] + ip[HIN+1]  *wp[4] + ip[HIN+2]  *wp[5];
            acc += ip[2*HIN]  *wp[6] + ip[2*HIN+1]*wp[7] + ip[2*HIN+2]*wp[8];
            ip += HIN*HIN;
            wp += 9;
        }
    } else {
        for (int ci = 0; ci < CI; ci++) {
            const float* ip = ib + (size_t)ci*HIN*HIN;
            const float* wp = sw + ci*9;
            #pragma unroll
            for (int ky = 0; ky < 3; ky++) {
                int iy = iy0 + ky;
                if ((unsigned)iy >= (unsigned)HIN) continue;
                #pragma unroll
                for (int kx = 0; kx < 3; kx++) {
                    int ix = ix0 + kx;
                    if ((unsigned)ix >= (unsigned)HIN) continue;
                    acc += ip[iy*HIN + ix] * wp[ky*3 + kx];
                }
            }
        }
    }
    out[(size_t)(b*CO + co)*PLANE + pix] = acc >= 0.f ? acc : 0.2f*acc;
}

// -------- warp-per-output conv (deep CI, small plane): lane owns ci slice ----
template<int CI, int CO, int HIN, int WPB>
__global__ __launch_bounds__(WPB*32) void convw_k(const float* __restrict__ in,
                       const float* __restrict__ w,
                       const float* __restrict__ bias, float* __restrict__ out) {
    const int HO = HIN / 2;
    const int PLANE = HO * HO;
    int gw   = blockIdx.x * WPB + (threadIdx.x >> 5);
    int lane = threadIdx.x & 31;
    if (gw >= BATCH*CO*PLANE) return;
    int pix = gw % PLANE;
    int co  = (gw / PLANE) % CO;
    int b   = gw / (PLANE * CO);
    int oy = pix / HO, ox = pix % HO;
    int iy0 = oy*2 - 1, ix0 = ox*2 - 1;

    float acc = 0.f;
    for (int ci = lane; ci < CI; ci += 32) {
        const float* ip = in + (size_t)(b*CI + ci)*HIN*HIN;
        const float* wp = w + (size_t)(co*CI + ci)*9;
        if (iy0 >= 0 && ix0 >= 0) {
            const float* p0 = ip + (size_t)iy0*HIN + ix0;
            acc += p0[0]     *wp[0] + p0[1]     *wp[1] + p0[2]     *wp[2];
            acc += p0[HIN]   *wp[3] + p0[HIN+1] *wp[4] + p0[HIN+2] *wp[5];
            acc += p0[2*HIN] *wp[6] + p0[2*HIN+1]*wp[7] + p0[2*HIN+2]*wp[8];
        } else {
            #pragma unroll
            for (int ky = 0; ky < 3; ky++) {
                int iy = iy0 + ky;
                if ((unsigned)iy >= (unsigned)HIN) continue;
                #pragma unroll
                for (int kx = 0; kx < 3; kx++) {
                    int ix = ix0 + kx;
                    if ((unsigned)ix >= (unsigned)HIN) continue;
                    acc += ip[iy*HIN + ix] * wp[ky*3 + kx];
                }
            }
        }
    }
    #pragma unroll
    for (int o = 16; o > 0; o >>= 1)
        acc += __shfl_down_sync(0xffffffffu, acc, o);
    if (lane == 0) {
        float v = acc + bias[co];
        out[(size_t)(b*CO + co)*PLANE + pix] = v >= 0.f ? v : 0.2f*v;
    }
}

// ---------------- instance norm, in place (block per (b,c)) ------------------
__global__ void inorm_k(float* __restrict__ x, const float* __restrict__ g,
                        const float* __restrict__ be, int C, int N) {
    int bc = blockIdx.x;
    int c  = bc % C;
    float* p = x + (size_t)bc * N;
    float s = 0.f, s2 = 0.f;
    for (int i = threadIdx.x; i < N; i += blockDim.x) { float v = p[i]; s += v; s2 += v*v; }
    __shared__ float sa[256], sb[256];
    sa[threadIdx.x] = s; sb[threadIdx.x] = s2;
    __syncthreads();
    for (int o = 128; o > 0; o >>= 1) {
        if (threadIdx.x < o) { sa[threadIdx.x] += sa[threadIdx.x+o]; sb[threadIdx.x] += sb[threadIdx.x+o]; }
        __syncthreads();
    }
    __shared__ float s_a, s_b;
    if (threadIdx.x == 0) {
        float m   = sa[0] / (float)N;
        float var = sb[0] / (float)N - m*m;
        float inv = rsqrtf(var + 1e-5f);
        float a   = inv * g[c];
        s_a = a;
        s_b = be[c] - m * a;
    }
    __syncthreads();
    float a = s_a, bt = s_b;
    for (int i = threadIdx.x; i < N; i += blockDim.x) p[i] = p[i]*a + bt;
}

// --- pool 8x8 -> (2,2), FCs (4-way split dot products), softmax+cumsum, tbl --
__global__ void fc_k(const float* __restrict__ wgen_w, const float* __restrict__ wgen_b,
                     const float* __restrict__ ada_w,  const float* __restrict__ ada_b) {
    int b = blockIdx.x;
    int t = threadIdx.x;
    __shared__ float sx[512];
    __shared__ float part[396];
    __shared__ float slog[96];
    __shared__ float sv[3*V];
    {
        int c  = t >> 2;
        int ij = t & 3;
        int i0 = (ij >> 1) * 4;
        int j0 = (ij & 1) * 4;
        const float* p = g_a5 + (size_t)(b*128 + c) * 64;
        float s = 0.f;
        #pragma unroll
        for (int pp = 0; pp < 4; pp++)
            #pragma unroll
            for (int qq = 0; qq < 4; qq++)
                s += p[(i0+pp)*8 + j0+qq];
        sx[t] = s * (1.f/16.f);
    }
    __syncthreads();
    if (t < 384) {
        int o = t >> 2, j = t & 3;
        float d = 0.f;
        int m0 = j * 128;
        for (int m = m0; m < m0 + 128; m++) d += sx[m] * ada_w[m*96 + o];
        part[t] = d;
    } else if (t < 396) {
        int r = t - 384;
        int n = r >> 2, j = r & 3;
        float d = 0.f;
        int m0 = j * 128;
        for (int m = m0; m < m0 + 128; m++) d += sx[m] * wgen_w[m*3 + n];
        part[384 + r] = d;
    }
    __syncthreads();
    if (t < 96) {
        slog[t] = ada_b[t] + part[4*t] + part[4*t+1] + part[4*t+2] + part[4*t+3];
    } else if (t < 99) {
        int n = t - 96;
        g_wts[b*3 + n] = wgen_b[n] + part[384+4*n] + part[384+4*n+1]
                       + part[384+4*n+2] + part[384+4*n+3];
    }
    __syncthreads();
    if (t < 3) {
        float mx = -1e30f;
        for (int k = 0; k < 32; k++) mx = fmaxf(mx, slog[t*32 + k]);
        float e[32]; float sum = 0.f;
        for (int k = 0; k < 32; k++) { e[k] = expf(slog[t*32 + k] - mx); sum += e[k]; }
        float isum = 1.f / sum;
        float* vp = g_vert + (b*3 + t) * V;
        sv[t*V] = 0.f;
        vp[0] = 0.f;
        float run = 0.f;
        for (int k = 0; k < 32; k++) {
            run += e[k]*isum;
            sv[t*V + k + 1] = run;
            vp[k+1] = run;
        }
    }
    __syncthreads();
    // folded inverse-table build: 3*256 entries per batch
    for (int i = t; i < 3*256; i += 512) {
        int c = i >> 8;
        int k = i & 255;
        const float* v = sv + c*V;
        float q = (float)k * (1.f/256.f);
        int pos = 0;
        #pragma unroll
        for (int sft = 16; sft >= 1; sft >>= 1)
            if (v[pos + sft] <= q) pos += sft;
        float4 e;
        e.x = (float)pos;
        e.y = v[pos];
        e.z = v[pos+1];
        e.w = 1.f / fmaxf(v[pos+1] - v[pos], 1e-10f);
        g_tbl[(b*3 + c)*256 + k] = e;
    }
}

// ---------------- build quad-packed fp16 LUT ---------------------------------
__global__ void lut_k(const float* __restrict__ basis_w) {
    int i = blockIdx.x * blockDim.x + threadIdx.x;
    if (i >= BATCH*V3) return;
    int b    = i / V3;
    int flat = i % V3;
    int ir   = flat % V;
    int ig   = (flat / V) % V;
    int dro  = (ir < V-1) ? 1 : 0;
    int dgo  = (ig < V-1) ? V : 0;
    int f00 = flat, f01 = flat + dro, f10 = flat + dgo, f11 = flat + dgo + dro;
    float w0 = g_wts[b*3+0], w1 = g_wts[b*3+1], w2 = g_wts[b*3+2];
    const float* bw = basis_w;
    #define LVAL(ch, f) (w0*bw[0*3*V3 + (ch)*V3 + (f)] + w1*bw[1*3*V3 + (ch)*V3 + (f)] + w2*bw[2*3*V3 + (ch)*V3 + (f)])
    __half2 r01 = __floats2half2_rn(LVAL(0, f00), LVAL(0, f01));
    __half2 r23 = __floats2half2_rn(LVAL(0, f10), LVAL(0, f11));
    __half2 g01 = __floats2half2_rn(LVAL(1, f00), LVAL(1, f01));
    __half2 g23 = __floats2half2_rn(LVAL(1, f10), LVAL(1, f11));
    __half2 b01 = __floats2half2_rn(LVAL(2, f00), LVAL(2, f01));
    __half2 b23 = __floats2half2_rn(LVAL(2, f10), LVAL(2, f11));
    #undef LVAL
    Lut4 o;
    o.rg = make_uint4(h2u(r01), h2u(r23), h2u(g01), h2u(g23));
    o.bb = make_uint2(h2u(b01), h2u(b23));
    o.pad = make_uint2(0u, 0u);
    g_lut4[i] = o;
}

// ---------------- trilinear LUT transform ------------------------------------
__device__ __forceinline__ void lut_lookup(const float4* __restrict__ tbl,
                                           const float* __restrict__ v, float q,
                                           int& idx, float& f) {
    q = fminf(fmaxf(q, 0.f), 1.f);
    int k = min(255, (int)(q * 256.f));
    float4 e = tbl[k];
    int   i  = (int)e.x;
    float v0 = e.y, v1 = e.z, inv = e.w;
    while (v1 <= q && i < 31) {
        i++; v0 = v1; v1 = v[i+1];
        inv = 1.f / fmaxf(v1 - v0, 1e-10f);
    }
    idx = i;
    f = fminf((q - v0) * inv, 1.f);
}

__device__ __forceinline__ float3 interp4(const Lut4* __restrict__ e,
        float w00, float w01, float w10, float w11) {
    uint4 rg = __ldg(&e->rg);
    uint2 bb = __ldg(&e->bb);
    float2 r01 = __half22float2(*reinterpret_cast<const __half2*>(&rg.x));
    float2 r23 = __half22float2(*reinterpret_cast<const __half2*>(&rg.y));
    float2 g01 = __half22float2(*reinterpret_cast<const __half2*>(&rg.z));
    float2 g23 = __half22float2(*reinterpret_cast<const __half2*>(&rg.w));
    float2 b01 = __half22float2(*reinterpret_cast<const __half2*>(&bb.x));
    float2 b23 = __half22float2(*reinterpret_cast<const __half2*>(&bb.y));
    float3 o;
    o.x = w00*r01.x + w01*r01.y + w10*r23.x + w11*r23.y;
    o.y = w00*g01.x + w01*g01.y + w10*g23.x + w11*g23.y;
    o.z = w00*b01.x + w01*b01.y + w10*b23.x + w11*b23.y;
    return o;
}

__device__ __forceinline__ float3 apply_px(float r, float g, float bl,
        const float4* __restrict__ tr, const float4* __restrict__ tg,
        const float4* __restrict__ tb,
        const float* __restrict__ vr, const float* __restrict__ vg,
        const float* __restrict__ vb, const Lut4* __restrict__ lb) {
    int ir, ig, ib;
    float fr, fg, fb;
    lut_lookup(tr, vr, r,  ir, fr);
    lut_lookup(tg, vg, g,  ig, fg);
    lut_lookup(tb, vb, bl, ib, fb);
    int base = (ib*V + ig)*V + ir;
    float w00 = (1.f-fg)*(1.f-fr);
    float w01 = (1.f-fg)*fr;
    float w10 = fg*(1.f-fr);
    float w11 = fg*fr;
    float3 lo = interp4(lb + base,       w00, w01, w10, w11);
    float3 hi = interp4(lb + base + V*V, w00, w01, w10, w11);
    float omfb = 1.f - fb;
    return make_float3(omfb*lo.x + fb*hi.x,
                       omfb*lo.y + fb*hi.y,
                       omfb*lo.z + fb*hi.z);
}

__global__ __launch_bounds__(256) void trans_k(const float* __restrict__ img,
                                               float* __restrict__ out) {
    __shared__ float4 stbl[3*256];
    __shared__ float  sv[3*V];
    const int PPT = 8;                                   // pixels per thread
    const int BPB = (NPIX/PPT) / 256;                    // blocks per batch = 2048
    int b   = blockIdx.x / BPB;
    int blk = blockIdx.x % BPB;

    for (int i = threadIdx.x; i < 3*256; i += 256) stbl[i] = g_tbl[b*3*256 + i];
    for (int i = threadIdx.x; i < 3*V;   i += 256) sv[i]   = g_vert[b*3*V + i];
    __syncthreads();

    int q8 = blk*256 + threadIdx.x;                      // chunk of 8 pixels
    int q  = q8 * 2;                                     // float4 index (2 per chunk)

    const float4* rp = (const float4*)(img + (size_t)(b*3+0)*NPIX);
    const float4* gp = (const float4*)(img + (size_t)(b*3+1)*NPIX);
    const float4* bp = (const float4*)(img + (size_t)(b*3+2)*NPIX);
    const float4* tr = stbl;
    const float4* tg = stbl + 256;
    const float4* tb = stbl + 512;
    const float*  vr = sv;
    const float*  vg = sv + V;
    const float*  vb = sv + 2*V;
    const Lut4*   lb = g_lut4 + (size_t)b*V3;

    float4* orp = (float4*)(out + (size_t)(b*3+0)*NPIX);
    float4* ogp = (float4*)(out + (size_t)(b*3+1)*NPIX);
    float4* obp = (float4*)(out + (size_t)(b*3+2)*NPIX);

    #pragma unroll
    for (int h = 0; h < 2; h++) {
        float4 R  = __ldcs(rp + q + h);
        float4 G  = __ldcs(gp + q + h);
        float4 Bl = __ldcs(bp + q + h);
        float3 o0 = apply_px(R.x, G.x, Bl.x, tr, tg, tb, vr, vg, vb, lb);
        float3 o1 = apply_px(R.y, G.y, Bl.y, tr, tg, tb, vr, vg, vb, lb);
        float3 o2 = apply_px(R.z, G.z, Bl.z, tr, tg, tb, vr, vg, vb, lb);
        float3 o3 = apply_px(R.w, G.w, Bl.w, tr, tg, tb, vr, vg, vb, lb);
        __stcs(orp + q + h, make_float4(o0.x, o1.x, o2.x, o3.x));
        __stcs(ogp + q + h, make_float4(o0.y, o1.y, o2.y, o3.y));
        __stcs(obp + q + h, make_float4(o0.z, o1.z, o2.z, o3.z));
    }
}

// ---------------- launch ------------------------------------------------------
extern "C" void kernel_launch(void* const* d_in, const int* in_sizes, int n_in,
                              void* d_out, int out_size) {
    const float* imgs   = (const float*)d_in[0];
    const float* w1 = (const float*)d_in[1];  const float* b1 = (const float*)d_in[2];
    const float* g1 = (const float*)d_in[3];  const float* be1 = (const float*)d_in[4];
    const float* w2 = (const float*)d_in[5];  const float* b2 = (const float*)d_in[6];
    const float* g2 = (const float*)d_in[7];  const float* be2 = (const float*)d_in[8];
    const float* w3 = (const float*)d_in[9];  const float* b3 = (const float*)d_in[10];
    const float* g3 = (const float*)d_in[11]; const float* be3 = (const float*)d_in[12];
    const float* w4 = (const float*)d_in[13]; const float* b4 = (const float*)d_in[14];
    const float* g4 = (const float*)d_in[15]; const float* be4 = (const float*)d_in[16];
    const float* w5 = (const float*)d_in[17]; const float* b5 = (const float*)d_in[18];
    const float* wgen_w = (const float*)d_in[19]; const float* wgen_b = (const float*)d_in[20];
    const float* basis_w = (const float*)d_in[21];
    const float* ada_w = (const float*)d_in[22]; const float* ada_b = (const float*)d_in[23];
    float* out = (float*)d_out;

    void *p_rs, *p_a1, *p_a2, *p_a3, *p_a4, *p_a5;
    cudaGetSymbolAddress(&p_rs, g_rs);
    cudaGetSymbolAddress(&p_a1, g_a1);
    cudaGetSymbolAddress(&p_a2, g_a2);
    cudaGetSymbolAddress(&p_a3, g_a3);
    cudaGetSymbolAddress(&p_a4, g_a4);
    cudaGetSymbolAddress(&p_a5, g_a5);

    const int T = 256;

    resize_k<<<(BATCH*3*256*256 + T-1)/T, T>>>(imgs);

    // shallow layers: thread-per-output with smem weights
    conv_k<3,  16, 256, 256><<<BATCH*16*(128*128/256), 256>>>((const float*)p_rs, w1, b1, (float*)p_a1);
    inorm_k<<<BATCH*16,  T>>>((float*)p_a1, g1, be1, 16, 128*128);
    conv_k<16, 32, 128, 256><<<BATCH*32*(64*64/256),   256>>>((const float*)p_a1, w2, b2, (float*)p_a2);
    inorm_k<<<BATCH*32,  T>>>((float*)p_a2, g2, be2, 32, 64*64);

    // deep layers: warp-per-output (8 warps/block)
    convw_k<32, 64, 64, 8 ><<<(BATCH*64*1024 + 7)/8,  256>>>((const float*)p_a2, w3, b3, (float*)p_a3);
    inorm_k<<<BATCH*64,  T>>>((float*)p_a3, g3, be3, 64, 32*32);
    convw_k<64, 128, 32, 8><<<(BATCH*128*256 + 7)/8,  256>>>((const float*)p_a3, w4, b4, (float*)p_a4);
    inorm_k<<<BATCH*128, T>>>((float*)p_a4, g4, be4, 128, 16*16);
    convw_k<128,128, 16, 8><<<(BATCH*128*64 + 7)/8,   256>>>((const float*)p_a4, w5, b5, (float*)p_a5);

    fc_k<<<BATCH, 512>>>(wgen_w, wgen_b, ada_w, ada_b);
    lut_k<<<(BATCH*V3 + T-1)/T, T>>>(basis_w);

    trans_k<<<BATCH*((NPIX/8)/256), 256>>>(imgs, out);
}

// round 9
// speedup vs baseline: 1.3896x; 1.3896x over previous
#include <cuda_runtime.h>
#include <cuda_fp16.h>
#include <cstdint>
#include <math.h>

#define V 33
#define V3 (V*V*V)          // 35937
#define BATCH 2
#define HW 2048
#define NPIX (HW*HW)

// ---------------- scratch (static device globals; no allocation) -------------
__device__ float  g_rs[BATCH*3*256*256];
__device__ float  g_a1[BATCH*16*128*128];
__device__ float  g_a2[BATCH*32*64*64];
__device__ float  g_a3[BATCH*64*32*32];
__device__ float  g_a4[BATCH*128*16*16];
__device__ float  g_a5[BATCH*128*8*8];
__device__ float  g_wts[BATCH*3];
__device__ float  g_vert[BATCH*3*V];
// dual-interval bin table: per (b,c,k): [0]={thr, ia, c0a, c1a} [1]={ib, c0b, c1b, 0}
__device__ float4 g_tbl[BATCH*3*256*2];

// quad-packed fp16 LUT: entry(flat=(ib,ig,ir)) holds the 4 (dg,dr) corners
struct alignas(32) Lut4 { uint4 rg; uint2 bb; uint2 pad; };
__device__ Lut4 g_lut4[BATCH*V3];

__device__ __forceinline__ unsigned int h2u(__half2 h) {
    return *reinterpret_cast<unsigned int*>(&h);
}

// ---------------- stage 1: bilinear 2048 -> 256 (scale exactly 8) ------------
__global__ void resize_k(const float* __restrict__ img) {
    int i = blockIdx.x * blockDim.x + threadIdx.x;
    if (i >= BATCH*3*256*256) return;
    int ox = i & 255;
    int oy = (i >> 8) & 255;
    int pc = i >> 16;                       // b*3 + c
    const float* p = img + (size_t)pc * NPIX;
    int iy = oy*8 + 3, ix = ox*8 + 3;
    float p00 = p[(size_t)iy*HW + ix];
    float p01 = p[(size_t)iy*HW + ix + 1];
    float p10 = p[(size_t)(iy+1)*HW + ix];
    float p11 = p[(size_t)(iy+1)*HW + ix + 1];
    float r0 = 0.5f*p00 + 0.5f*p10;
    float r1 = 0.5f*p01 + 0.5f*p11;
    g_rs[i] = 0.5f*r0 + 0.5f*r1;
}

// ------- thread-per-output conv, weights in smem (R5 proven form) ------------
template<int CI, int CO, int HIN, int TPB>
__global__ __launch_bounds__(TPB) void conv_k(const float* __restrict__ in,
                       const float* __restrict__ w,
                       const float* __restrict__ bias, float* __restrict__ out) {
    const int HO = HIN / 2;
    const int PLANE = HO * HO;
    const int BPP = PLANE / TPB;
    int blk  = blockIdx.x;
    int pix  = (blk % BPP) * TPB + threadIdx.x;
    int co   = (blk / BPP) % CO;
    int b    = blk / (BPP * CO);

    __shared__ float sw[CI*9];
    for (int i = threadIdx.x; i < CI*9; i += TPB) sw[i] = w[(size_t)co*CI*9 + i];
    __syncthreads();

    int ox = pix % HO;
    int oy = pix / HO;
    float acc = bias[co];
    const float* ib = in + (size_t)b*CI*HIN*HIN;
    int iy0 = oy*2 - 1, ix0 = ox*2 - 1;
    if (iy0 >= 0 && ix0 >= 0) {
        const float* ip = ib + (size_t)iy0*HIN + ix0;
        const float* wp = sw;
        for (int ci = 0; ci < CI; ci++) {
            acc += ip[0]      *wp[0] + ip[1]      *wp[1] + ip[2]      *wp[2];
            acc += ip[HIN]    *wp[3] + ip[HIN+1]  *wp[4] + ip[HIN+2]  *wp[5];
            acc += ip[2*HIN]  *wp[6] + ip[2*HIN+1]*wp[7] + ip[2*HIN+2]*wp[8];
            ip += HIN*HIN;
            wp += 9;
        }
    } else {
        for (int ci = 0; ci < CI; ci++) {
            const float* ip = ib + (size_t)ci*HIN*HIN;
            const float* wp = sw + ci*9;
            #pragma unroll
            for (int ky = 0; ky < 3; ky++) {
                int iy = iy0 + ky;
                if ((unsigned)iy >= (unsigned)HIN) continue;
                #pragma unroll
                for (int kx = 0; kx < 3; kx++) {
                    int ix = ix0 + kx;
                    if ((unsigned)ix >= (unsigned)HIN) continue;
                    acc += ip[iy*HIN + ix] * wp[ky*3 + kx];
                }
            }
        }
    }
    out[(size_t)(b*CO + co)*PLANE + pix] = acc >= 0.f ? acc : 0.2f*acc;
}

// ---------------- instance norm, in place (block per (b,c)) ------------------
__global__ void inorm_k(float* __restrict__ x, const float* __restrict__ g,
                        const float* __restrict__ be, int C, int N) {
    int bc = blockIdx.x;
    int c  = bc % C;
    float* p = x + (size_t)bc * N;
    float s = 0.f, s2 = 0.f;
    for (int i = threadIdx.x; i < N; i += blockDim.x) { float v = p[i]; s += v; s2 += v*v; }
    __shared__ float sa[256], sb[256];
    sa[threadIdx.x] = s; sb[threadIdx.x] = s2;
    __syncthreads();
    for (int o = 128; o > 0; o >>= 1) {
        if (threadIdx.x < o) { sa[threadIdx.x] += sa[threadIdx.x+o]; sb[threadIdx.x] += sb[threadIdx.x+o]; }
        __syncthreads();
    }
    __shared__ float s_a, s_b;
    if (threadIdx.x == 0) {
        float m   = sa[0] / (float)N;
        float var = sb[0] / (float)N - m*m;
        float inv = rsqrtf(var + 1e-5f);
        float a   = inv * g[c];
        s_a = a;
        s_b = be[c] - m * a;
    }
    __syncthreads();
    float a = s_a, bt = s_b;
    for (int i = threadIdx.x; i < N; i += blockDim.x) p[i] = p[i]*a + bt;
}

// --- pool 8x8 -> (2,2), FCs (4-way split), softmax+cumsum, dual-bin table ----
__global__ void fc_k(const float* __restrict__ wgen_w, const float* __restrict__ wgen_b,
                     const float* __restrict__ ada_w,  const float* __restrict__ ada_b) {
    int b = blockIdx.x;
    int t = threadIdx.x;
    __shared__ float sx[512];
    __shared__ float part[396];
    __shared__ float slog[96];
    __shared__ float sv[3*V];
    {
        int c  = t >> 2;
        int ij = t & 3;
        int i0 = (ij >> 1) * 4;
        int j0 = (ij & 1) * 4;
        const float* p = g_a5 + (size_t)(b*128 + c) * 64;
        float s = 0.f;
        #pragma unroll
        for (int pp = 0; pp < 4; pp++)
            #pragma unroll
            for (int qq = 0; qq < 4; qq++)
                s += p[(i0+pp)*8 + j0+qq];
        sx[t] = s * (1.f/16.f);
    }
    __syncthreads();
    if (t < 384) {
        int o = t >> 2, j = t & 3;
        float d = 0.f;
        int m0 = j * 128;
        for (int m = m0; m < m0 + 128; m++) d += sx[m] * ada_w[m*96 + o];
        part[t] = d;
    } else if (t < 396) {
        int r = t - 384;
        int n = r >> 2, j = r & 3;
        float d = 0.f;
        int m0 = j * 128;
        for (int m = m0; m < m0 + 128; m++) d += sx[m] * wgen_w[m*3 + n];
        part[384 + r] = d;
    }
    __syncthreads();
    if (t < 96) {
        slog[t] = ada_b[t] + part[4*t] + part[4*t+1] + part[4*t+2] + part[4*t+3];
    } else if (t < 99) {
        int n = t - 96;
        g_wts[b*3 + n] = wgen_b[n] + part[384+4*n] + part[384+4*n+1]
                       + part[384+4*n+2] + part[384+4*n+3];
    }
    __syncthreads();
    if (t < 3) {
        float mx = -1e30f;
        for (int k = 0; k < 32; k++) mx = fmaxf(mx, slog[t*32 + k]);
        float e[32]; float sum = 0.f;
        for (int k = 0; k < 32; k++) { e[k] = expf(slog[t*32 + k] - mx); sum += e[k]; }
        float isum = 1.f / sum;
        float* vp = g_vert + (b*3 + t) * V;
        sv[t*V] = 0.f;
        vp[0] = 0.f;
        float run = 0.f;
        for (int k = 0; k < 32; k++) {
            run += e[k]*isum;
            sv[t*V + k + 1] = run;
            vp[k+1] = run;
        }
    }
    __syncthreads();
    // dual-interval bin table: exact branchless lookup support
    for (int i = t; i < 3*256; i += 512) {
        int c = i >> 8;
        int k = i & 255;
        const float* v = sv + c*V;
        float qlo = (float)k * (1.f/256.f);
        int pos = 0;
        #pragma unroll
        for (int sft = 16; sft >= 1; sft >>= 1)
            if (v[pos + sft] <= qlo) pos += sft;
        // interval A = pos  (valid while q < thr = v[pos+1])
        float thr  = v[pos+1];
        float c1a  = 1.f / fmaxf(v[pos+1] - v[pos], 1e-10f);
        float c0a  = -v[pos] * c1a;
        // interval B = min(pos+1, 31)  (valid when q >= thr)
        int   ibx  = pos + 1 <= 31 ? pos + 1 : 31;
        float c1b  = 1.f / fmaxf(v[ibx+1] - v[ibx], 1e-10f);
        float c0b  = -v[ibx] * c1b;
        int base = ((b*3 + c)*256 + k)*2;
        g_tbl[base]   = make_float4(thr, (float)pos, c0a, c1a);
        g_tbl[base+1] = make_float4((float)ibx, c0b, c1b, 0.f);
    }
}

// ---------------- build quad-packed fp16 LUT ---------------------------------
__global__ void lut_k(const float* __restrict__ basis_w) {
    int i = blockIdx.x * blockDim.x + threadIdx.x;
    if (i >= BATCH*V3) return;
    int b    = i / V3;
    int flat = i % V3;
    int ir   = flat % V;
    int ig   = (flat / V) % V;
    int dro  = (ir < V-1) ? 1 : 0;
    int dgo  = (ig < V-1) ? V : 0;
    int f00 = flat, f01 = flat + dro, f10 = flat + dgo, f11 = flat + dgo + dro;
    float w0 = g_wts[b*3+0], w1 = g_wts[b*3+1], w2 = g_wts[b*3+2];
    const float* bw = basis_w;
    #define LVAL(ch, f) (w0*bw[0*3*V3 + (ch)*V3 + (f)] + w1*bw[1*3*V3 + (ch)*V3 + (f)] + w2*bw[2*3*V3 + (ch)*V3 + (f)])
    __half2 r01 = __floats2half2_rn(LVAL(0, f00), LVAL(0, f01));
    __half2 r23 = __floats2half2_rn(LVAL(0, f10), LVAL(0, f11));
    __half2 g01 = __floats2half2_rn(LVAL(1, f00), LVAL(1, f01));
    __half2 g23 = __floats2half2_rn(LVAL(1, f10), LVAL(1, f11));
    __half2 b01 = __floats2half2_rn(LVAL(2, f00), LVAL(2, f01));
    __half2 b23 = __floats2half2_rn(LVAL(2, f10), LVAL(2, f11));
    #undef LVAL
    Lut4 o;
    o.rg = make_uint4(h2u(r01), h2u(r23), h2u(g01), h2u(g23));
    o.bb = make_uint2(h2u(b01), h2u(b23));
    o.pad = make_uint2(0u, 0u);
    g_lut4[i] = o;
}

// ---------------- trilinear LUT transform ------------------------------------
// branchless exact lookup from dual-interval bin table (per-channel base tbl)
__device__ __forceinline__ void lut_lookup(const float4* __restrict__ tbl,
                                           float q, int& idx, float& f) {
    q = __saturatef(q);
    int k = min(255, (int)(q * 256.f));
    float4 e0 = tbl[k*2];
    float4 e1 = tbl[k*2+1];
    bool up = q >= e0.x;
    float fi = up ? e1.x : e0.y;
    float c0 = up ? e1.y : e0.z;
    float c1 = up ? e1.z : e0.w;
    idx = (int)fi;
    f = __saturatef(fmaf(q, c1, c0));
}

__device__ __forceinline__ float3 interp4(const Lut4* __restrict__ e,
        float w00, float w01, float w10, float w11) {
    uint4 rg = __ldg(&e->rg);
    uint2 bb = __ldg(&e->bb);
    float2 r01 = __half22float2(*reinterpret_cast<const __half2*>(&rg.x));
    float2 r23 = __half22float2(*reinterpret_cast<const __half2*>(&rg.y));
    float2 g01 = __half22float2(*reinterpret_cast<const __half2*>(&rg.z));
    float2 g23 = __half22float2(*reinterpret_cast<const __half2*>(&rg.w));
    float2 b01 = __half22float2(*reinterpret_cast<const __half2*>(&bb.x));
    float2 b23 = __half22float2(*reinterpret_cast<const __half2*>(&bb.y));
    float3 o;
    o.x = w00*r01.x + w01*r01.y + w10*r23.x + w11*r23.y;
    o.y = w00*g01.x + w01*g01.y + w10*g23.x + w11*g23.y;
    o.z = w00*b01.x + w01*b01.y + w10*b23.x + w11*b23.y;
    return o;
}

__device__ __forceinline__ float3 apply_px(float r, float g, float bl,
        const float4* __restrict__ tr, const float4* __restrict__ tg,
        const float4* __restrict__ tb, const Lut4* __restrict__ lb) {
    int ir, ig, ib;
    float fr, fg, fb;
    lut_lookup(tr, r,  ir, fr);
    lut_lookup(tg, g,  ig, fg);
    lut_lookup(tb, bl, ib, fb);
    int base = (ib*V + ig)*V + ir;
    float w00 = (1.f-fg)*(1.f-fr);
    float w01 = (1.f-fg)*fr;
    float w10 = fg*(1.f-fr);
    float w11 = fg*fr;
    float3 lo = interp4(lb + base,       w00, w01, w10, w11);
    float3 hi = interp4(lb + base + V*V, w00, w01, w10, w11);
    float omfb = 1.f - fb;
    return make_float3(omfb*lo.x + fb*hi.x,
                       omfb*lo.y + fb*hi.y,
                       omfb*lo.z + fb*hi.z);
}

__global__ __launch_bounds__(256) void trans_k(const float* __restrict__ img,
                                               float* __restrict__ out) {
    __shared__ float4 stbl[3*512];
    const int PPT = 8;                                   // pixels per thread
    const int BPB = (NPIX/PPT) / 256;                    // blocks per batch = 2048
    int b   = blockIdx.x / BPB;
    int blk = blockIdx.x % BPB;

    for (int i = threadIdx.x; i < 3*512; i += 256) stbl[i] = g_tbl[b*3*512 + i];
    __syncthreads();

    int q8 = blk*256 + threadIdx.x;                      // chunk of 8 pixels
    int q  = q8 * 2;                                     // float4 index (2 per chunk)

    const float4* rp = (const float4*)(img + (size_t)(b*3+0)*NPIX);
    const float4* gp = (const float4*)(img + (size_t)(b*3+1)*NPIX);
    const float4* bp = (const float4*)(img + (size_t)(b*3+2)*NPIX);
    const float4* tr = stbl;
    const float4* tg = stbl + 512;
    const float4* tb = stbl + 1024;
    const Lut4*   lb = g_lut4 + (size_t)b*V3;

    float4* orp = (float4*)(out + (size_t)(b*3+0)*NPIX);
    float4* ogp = (float4*)(out + (size_t)(b*3+1)*NPIX);
    float4* obp = (float4*)(out + (size_t)(b*3+2)*NPIX);

    #pragma unroll
    for (int h = 0; h < 2; h++) {
        float4 R = rp[q+h], G = gp[q+h], Bl = bp[q+h];
        float3 o0 = apply_px(R.x, G.x, Bl.x, tr, tg, tb, lb);
        float3 o1 = apply_px(R.y, G.y, Bl.y, tr, tg, tb, lb);
        float3 o2 = apply_px(R.z, G.z, Bl.z, tr, tg, tb, lb);
        float3 o3 = apply_px(R.w, G.w, Bl.w, tr, tg, tb, lb);
        orp[q+h] = make_float4(o0.x, o1.x, o2.x, o3.x);
        ogp[q+h] = make_float4(o0.y, o1.y, o2.y, o3.y);
        obp[q+h] = make_float4(o0.z, o1.z, o2.z, o3.z);
    }
}

// ---------------- launch ------------------------------------------------------
extern "C" void kernel_launch(void* const* d_in, const int* in_sizes, int n_in,
                              void* d_out, int out_size) {
    const float* imgs   = (const float*)d_in[0];
    const float* w1 = (const float*)d_in[1];  const float* b1 = (const float*)d_in[2];
    const float* g1 = (const float*)d_in[3];  const float* be1 = (const float*)d_in[4];
    const float* w2 = (const float*)d_in[5];  const float* b2 = (const float*)d_in[6];
    const float* g2 = (const float*)d_in[7];  const float* be2 = (const float*)d_in[8];
    const float* w3 = (const float*)d_in[9];  const float* b3 = (const float*)d_in[10];
    const float* g3 = (const float*)d_in[11]; const float* be3 = (const float*)d_in[12];
    const float* w4 = (const float*)d_in[13]; const float* b4 = (const float*)d_in[14];
    const float* g4 = (const float*)d_in[15]; const float* be4 = (const float*)d_in[16];
    const float* w5 = (const float*)d_in[17]; const float* b5 = (const float*)d_in[18];
    const float* wgen_w = (const float*)d_in[19]; const float* wgen_b = (const float*)d_in[20];
    const float* basis_w = (const float*)d_in[21];
    const float* ada_w = (const float*)d_in[22]; const float* ada_b = (const float*)d_in[23];
    float* out = (float*)d_out;

    void *p_rs, *p_a1, *p_a2, *p_a3, *p_a4, *p_a5;
    cudaGetSymbolAddress(&p_rs, g_rs);
    cudaGetSymbolAddress(&p_a1, g_a1);
    cudaGetSymbolAddress(&p_a2, g_a2);
    cudaGetSymbolAddress(&p_a3, g_a3);
    cudaGetSymbolAddress(&p_a4, g_a4);
    cudaGetSymbolAddress(&p_a5, g_a5);

    const int T = 256;

    resize_k<<<(BATCH*3*256*256 + T-1)/T, T>>>(imgs);

    conv_k<3,  16, 256, 256><<<BATCH*16*(128*128/256), 256>>>((const float*)p_rs, w1, b1, (float*)p_a1);
    inorm_k<<<BATCH*16,  T>>>((float*)p_a1, g1, be1, 16, 128*128);
    conv_k<16, 32, 128, 256><<<BATCH*32*(64*64/256),   256>>>((const float*)p_a1, w2, b2, (float*)p_a2);
    inorm_k<<<BATCH*32,  T>>>((float*)p_a2, g2, be2, 32, 64*64);
    conv_k<32, 64, 64, 256><<<BATCH*64*(32*32/256),    256>>>((const float*)p_a2, w3, b3, (float*)p_a3);
    inorm_k<<<BATCH*64,  T>>>((float*)p_a3, g3, be3, 64, 32*32);
    conv_k<64, 128, 32, 256><<<BATCH*128*(16*16/256),  256>>>((const float*)p_a3, w4, b4, (float*)p_a4);
    inorm_k<<<BATCH*128, T>>>((float*)p_a4, g4, be4, 128, 16*16);
    conv_k<128,128, 16, 64><<<BATCH*128*(8*8/64),      64>>>((const float*)p_a4, w5, b5, (float*)p_a5);

    fc_k<<<BATCH, 512>>>(wgen_w, wgen_b, ada_w, ada_b);
    lut_k<<<(BATCH*V3 + T-1)/T, T>>>(basis_w);

    trans_k<<<BATCH*((NPIX/8)/256), 256>>>(imgs, out);
}

// round 10
// speedup vs baseline: 1.5190x; 1.0932x over previous
#include <cuda_runtime.h>
#include <cuda_fp16.h>
#include <cstdint>
#include <math.h>

#define V 33
#define V3 (V*V*V)          // 35937
#define BATCH 2
#define HW 2048
#define NPIX (HW*HW)

// ---------------- scratch (static device globals; no allocation) -------------
__device__ float  g_rs[BATCH*3*256*256];
__device__ float  g_a1[BATCH*16*128*128];
__device__ float  g_a2[BATCH*32*64*64];
__device__ float  g_a3[BATCH*64*32*32];
__device__ float  g_a4[BATCH*128*16*16];
__device__ float  g_a5[BATCH*128*8*8];
__device__ float  g_wts[BATCH*3];
__device__ float  g_vert[BATCH*3*V];
// abs-kink bin table: per (b,c,k): {m0, m1, d1, qstar}; s(q)=m0+m1*q+d1*|q-qstar|
__device__ float4 g_tbl[BATCH*3*256];

// quad-packed fp16 LUT: entry(flat=(ib,ig,ir)) holds the 4 (dg,dr) corners
struct alignas(32) Lut4 { uint4 rg; uint2 bb; uint2 pad; };
__device__ Lut4 g_lut4[BATCH*V3];

__device__ __forceinline__ unsigned int h2u(__half2 h) {
    return *reinterpret_cast<unsigned int*>(&h);
}

// ---------------- stage 1: bilinear 2048 -> 256 (scale exactly 8) ------------
__global__ void resize_k(const float* __restrict__ img) {
    int i = blockIdx.x * blockDim.x + threadIdx.x;
    if (i >= BATCH*3*256*256) return;
    int ox = i & 255;
    int oy = (i >> 8) & 255;
    int pc = i >> 16;                       // b*3 + c
    const float* p = img + (size_t)pc * NPIX;
    int iy = oy*8 + 3, ix = ox*8 + 3;
    float p00 = p[(size_t)iy*HW + ix];
    float p01 = p[(size_t)iy*HW + ix + 1];
    float p10 = p[(size_t)(iy+1)*HW + ix];
    float p11 = p[(size_t)(iy+1)*HW + ix + 1];
    float r0 = 0.5f*p00 + 0.5f*p10;
    float r1 = 0.5f*p01 + 0.5f*p11;
    g_rs[i] = 0.5f*r0 + 0.5f*r1;
}

// ------- thread-per-output conv, weights in smem (R5 proven form) ------------
template<int CI, int CO, int HIN, int TPB>
__global__ __launch_bounds__(TPB) void conv_k(const float* __restrict__ in,
                       const float* __restrict__ w,
                       const float* __restrict__ bias, float* __restrict__ out) {
    const int HO = HIN / 2;
    const int PLANE = HO * HO;
    const int BPP = PLANE / TPB;
    int blk  = blockIdx.x;
    int pix  = (blk % BPP) * TPB + threadIdx.x;
    int co   = (blk / BPP) % CO;
    int b    = blk / (BPP * CO);

    __shared__ float sw[CI*9];
    for (int i = threadIdx.x; i < CI*9; i += TPB) sw[i] = w[(size_t)co*CI*9 + i];
    __syncthreads();

    int ox = pix % HO;
    int oy = pix / HO;
    float acc = bias[co];
    const float* ib = in + (size_t)b*CI*HIN*HIN;
    int iy0 = oy*2 - 1, ix0 = ox*2 - 1;
    if (iy0 >= 0 && ix0 >= 0) {
        const float* ip = ib + (size_t)iy0*HIN + ix0;
        const float* wp = sw;
        for (int ci = 0; ci < CI; ci++) {
            acc += ip[0]      *wp[0] + ip[1]      *wp[1] + ip[2]      *wp[2];
            acc += ip[HIN]    *wp[3] + ip[HIN+1]  *wp[4] + ip[HIN+2]  *wp[5];
            acc += ip[2*HIN]  *wp[6] + ip[2*HIN+1]*wp[7] + ip[2*HIN+2]*wp[8];
            ip += HIN*HIN;
            wp += 9;
        }
    } else {
        for (int ci = 0; ci < CI; ci++) {
            const float* ip = ib + (size_t)ci*HIN*HIN;
            const float* wp = sw + ci*9;
            #pragma unroll
            for (int ky = 0; ky < 3; ky++) {
                int iy = iy0 + ky;
                if ((unsigned)iy >= (unsigned)HIN) continue;
                #pragma unroll
                for (int kx = 0; kx < 3; kx++) {
                    int ix = ix0 + kx;
                    if ((unsigned)ix >= (unsigned)HIN) continue;
                    acc += ip[iy*HIN + ix] * wp[ky*3 + kx];
                }
            }
        }
    }
    out[(size_t)(b*CO + co)*PLANE + pix] = acc >= 0.f ? acc : 0.2f*acc;
}

// ---------------- instance norm, in place (block per (b,c)) ------------------
__global__ void inorm_k(float* __restrict__ x, const float* __restrict__ g,
                        const float* __restrict__ be, int C, int N) {
    int bc = blockIdx.x;
    int c  = bc % C;
    float* p = x + (size_t)bc * N;
    float s = 0.f, s2 = 0.f;
    for (int i = threadIdx.x; i < N; i += blockDim.x) { float v = p[i]; s += v; s2 += v*v; }
    __shared__ float sa[256], sb[256];
    sa[threadIdx.x] = s; sb[threadIdx.x] = s2;
    __syncthreads();
    for (int o = 128; o > 0; o >>= 1) {
        if (threadIdx.x < o) { sa[threadIdx.x] += sa[threadIdx.x+o]; sb[threadIdx.x] += sb[threadIdx.x+o]; }
        __syncthreads();
    }
    __shared__ float s_a, s_b;
    if (threadIdx.x == 0) {
        float m   = sa[0] / (float)N;
        float var = sb[0] / (float)N - m*m;
        float inv = rsqrtf(var + 1e-5f);
        float a   = inv * g[c];
        s_a = a;
        s_b = be[c] - m * a;
    }
    __syncthreads();
    float a = s_a, bt = s_b;
    for (int i = threadIdx.x; i < N; i += blockDim.x) p[i] = p[i]*a + bt;
}

// --- pool 8x8 -> (2,2), FCs (4-way split), softmax+cumsum, abs-kink table ----
__global__ void fc_k(const float* __restrict__ wgen_w, const float* __restrict__ wgen_b,
                     const float* __restrict__ ada_w,  const float* __restrict__ ada_b) {
    int b = blockIdx.x;
    int t = threadIdx.x;
    __shared__ float sx[512];
    __shared__ float part[396];
    __shared__ float slog[96];
    __shared__ float sv[3*V];
    {
        int c  = t >> 2;
        int ij = t & 3;
        int i0 = (ij >> 1) * 4;
        int j0 = (ij & 1) * 4;
        const float* p = g_a5 + (size_t)(b*128 + c) * 64;
        float s = 0.f;
        #pragma unroll
        for (int pp = 0; pp < 4; pp++)
            #pragma unroll
            for (int qq = 0; qq < 4; qq++)
                s += p[(i0+pp)*8 + j0+qq];
        sx[t] = s * (1.f/16.f);
    }
    __syncthreads();
    if (t < 384) {
        int o = t >> 2, j = t & 3;
        float d = 0.f;
        int m0 = j * 128;
        for (int m = m0; m < m0 + 128; m++) d += sx[m] * ada_w[m*96 + o];
        part[t] = d;
    } else if (t < 396) {
        int r = t - 384;
        int n = r >> 2, j = r & 3;
        float d = 0.f;
        int m0 = j * 128;
        for (int m = m0; m < m0 + 128; m++) d += sx[m] * wgen_w[m*3 + n];
        part[384 + r] = d;
    }
    __syncthreads();
    if (t < 96) {
        slog[t] = ada_b[t] + part[4*t] + part[4*t+1] + part[4*t+2] + part[4*t+3];
    } else if (t < 99) {
        int n = t - 96;
        g_wts[b*3 + n] = wgen_b[n] + part[384+4*n] + part[384+4*n+1]
                       + part[384+4*n+2] + part[384+4*n+3];
    }
    __syncthreads();
    if (t < 3) {
        float mx = -1e30f;
        for (int k = 0; k < 32; k++) mx = fmaxf(mx, slog[t*32 + k]);
        float e[32]; float sum = 0.f;
        for (int k = 0; k < 32; k++) { e[k] = expf(slog[t*32 + k] - mx); sum += e[k]; }
        float isum = 1.f / sum;
        float* vp = g_vert + (b*3 + t) * V;
        sv[t*V] = 0.f;
        vp[0] = 0.f;
        float run = 0.f;
        for (int k = 0; k < 32; k++) {
            run += e[k]*isum;
            sv[t*V + k + 1] = run;
            vp[k+1] = run;
        }
    }
    __syncthreads();
    // abs-kink bin table: s(q) = m0 + m1*q + d1*|q - qstar|, exact (<=1 vertex/bin)
    for (int i = t; i < 3*256; i += 512) {
        int c = i >> 8;
        int k = i & 255;
        const float* v = sv + c*V;
        float qlo = (float)k * (1.f/256.f);
        float qhi = (float)(k+1) * (1.f/256.f);
        int pos = 0;
        #pragma unroll
        for (int sft = 16; sft >= 1; sft >>= 1)
            if (v[pos + sft] <= qlo) pos += sft;
        float c1a = 1.f / fmaxf(v[pos+1] - v[pos], 1e-10f);
        float a0  = (float)pos - v[pos] * c1a;
        float m0 = a0, m1 = c1a, d1 = 0.f, qs = 0.f;
        float thr = v[pos+1];
        if (thr < qhi && pos < 31) {
            int   ibx = pos + 1;
            float c1b = 1.f / fmaxf(v[ibx+1] - v[ibx], 1e-10f);
            float b0  = (float)ibx - v[ibx] * c1b;
            m0 = 0.5f*(a0 + b0);
            m1 = 0.5f*(c1a + c1b);
            d1 = 0.5f*(c1b - c1a);
            qs = thr;
        }
        g_tbl[(b*3 + c)*256 + k] = make_float4(m0, m1, d1, qs);
    }
}

// ---------------- build quad-packed fp16 LUT ---------------------------------
__global__ void lut_k(const float* __restrict__ basis_w) {
    int i = blockIdx.x * blockDim.x + threadIdx.x;
    if (i >= BATCH*V3) return;
    int b    = i / V3;
    int flat = i % V3;
    int ir   = flat % V;
    int ig   = (flat / V) % V;
    int dro  = (ir < V-1) ? 1 : 0;
    int dgo  = (ig < V-1) ? V : 0;
    int f00 = flat, f01 = flat + dro, f10 = flat + dgo, f11 = flat + dgo + dro;
    float w0 = g_wts[b*3+0], w1 = g_wts[b*3+1], w2 = g_wts[b*3+2];
    const float* bw = basis_w;
    #define LVAL(ch, f) (w0*bw[0*3*V3 + (ch)*V3 + (f)] + w1*bw[1*3*V3 + (ch)*V3 + (f)] + w2*bw[2*3*V3 + (ch)*V3 + (f)])
    __half2 r01 = __floats2half2_rn(LVAL(0, f00), LVAL(0, f01));
    __half2 r23 = __floats2half2_rn(LVAL(0, f10), LVAL(0, f11));
    __half2 g01 = __floats2half2_rn(LVAL(1, f00), LVAL(1, f01));
    __half2 g23 = __floats2half2_rn(LVAL(1, f10), LVAL(1, f11));
    __half2 b01 = __floats2half2_rn(LVAL(2, f00), LVAL(2, f01));
    __half2 b23 = __floats2half2_rn(LVAL(2, f10), LVAL(2, f11));
    #undef LVAL
    Lut4 o;
    o.rg = make_uint4(h2u(r01), h2u(r23), h2u(g01), h2u(g23));
    o.bb = make_uint2(h2u(b01), h2u(b23));
    o.pad = make_uint2(0u, 0u);
    g_lut4[i] = o;
}

// ---------------- trilinear LUT transform ------------------------------------
// exact branchless lookup: one LDS.128, s = m0 + m1*q + d1*|q - qstar|
__device__ __forceinline__ void lut_lookup(const float4* __restrict__ tbl,
                                           float q, int& idx, float& f) {
    q = __saturatef(q);
    int k = min(255, (int)(q * 256.f));
    float4 e = tbl[k];
    float s = fmaf(e.y, q, e.x) + e.z * fabsf(q - e.w);
    int i = min((int)s, 31);
    idx = i;
    f = __saturatef(s - (float)i);
}

__device__ __forceinline__ float3 interp4(const Lut4* __restrict__ e,
        float w00, float w01, float w10, float w11) {
    uint4 rg = __ldg(&e->rg);
    uint2 bb = __ldg(&e->bb);
    float2 r01 = __half22float2(*reinterpret_cast<const __half2*>(&rg.x));
    float2 r23 = __half22float2(*reinterpret_cast<const __half2*>(&rg.y));
    float2 g01 = __half22float2(*reinterpret_cast<const __half2*>(&rg.z));
    float2 g23 = __half22float2(*reinterpret_cast<const __half2*>(&rg.w));
    float2 b01 = __half22float2(*reinterpret_cast<const __half2*>(&bb.x));
    float2 b23 = __half22float2(*reinterpret_cast<const __half2*>(&bb.y));
    float3 o;
    o.x = w00*r01.x + w01*r01.y + w10*r23.x + w11*r23.y;
    o.y = w00*g01.x + w01*g01.y + w10*g23.x + w11*g23.y;
    o.z = w00*b01.x + w01*b01.y + w10*b23.x + w11*b23.y;
    return o;
}

__device__ __forceinline__ float3 apply_px(float r, float g, float bl,
        const float4* __restrict__ tr, const float4* __restrict__ tg,
        const float4* __restrict__ tb, const Lut4* __restrict__ lb) {
    int ir, ig, ib;
    float fr, fg, fb;
    lut_lookup(tr, r,  ir, fr);
    lut_lookup(tg, g,  ig, fg);
    lut_lookup(tb, bl, ib, fb);
    int base = (ib*V + ig)*V + ir;
    float w00 = (1.f-fg)*(1.f-fr);
    float w01 = (1.f-fg)*fr;
    float w10 = fg*(1.f-fr);
    float w11 = fg*fr;
    float3 lo = interp4(lb + base,       w00, w01, w10, w11);
    float3 hi = interp4(lb + base + V*V, w00, w01, w10, w11);
    float omfb = 1.f - fb;
    return make_float3(omfb*lo.x + fb*hi.x,
                       omfb*lo.y + fb*hi.y,
                       omfb*lo.z + fb*hi.z);
}

__global__ __launch_bounds__(256) void trans_k(const float* __restrict__ img,
                                               float* __restrict__ out) {
    __shared__ float4 stbl[3*256];
    const int PPT = 8;                                   // pixels per thread
    const int BPB = (NPIX/PPT) / 256;                    // blocks per batch = 2048
    int b   = blockIdx.x / BPB;
    int blk = blockIdx.x % BPB;

    for (int i = threadIdx.x; i < 3*256; i += 256) stbl[i] = g_tbl[b*3*256 + i];
    __syncthreads();

    int q8 = blk*256 + threadIdx.x;                      // chunk of 8 pixels
    int q  = q8 * 2;                                     // float4 index (2 per chunk)

    const float4* rp = (const float4*)(img + (size_t)(b*3+0)*NPIX);
    const float4* gp = (const float4*)(img + (size_t)(b*3+1)*NPIX);
    const float4* bp = (const float4*)(img + (size_t)(b*3+2)*NPIX);
    const float4* tr = stbl;
    const float4* tg = stbl + 256;
    const float4* tb = stbl + 512;
    const Lut4*   lb = g_lut4 + (size_t)b*V3;

    float4* orp = (float4*)(out + (size_t)(b*3+0)*NPIX);
    float4* ogp = (float4*)(out + (size_t)(b*3+1)*NPIX);
    float4* obp = (float4*)(out + (size_t)(b*3+2)*NPIX);

    #pragma unroll
    for (int h = 0; h < 2; h++) {
        float4 R = rp[q+h], G = gp[q+h], Bl = bp[q+h];
        float3 o0 = apply_px(R.x, G.x, Bl.x, tr, tg, tb, lb);
        float3 o1 = apply_px(R.y, G.y, Bl.y, tr, tg, tb, lb);
        float3 o2 = apply_px(R.z, G.z, Bl.z, tr, tg, tb, lb);
        float3 o3 = apply_px(R.w, G.w, Bl.w, tr, tg, tb, lb);
        orp[q+h] = make_float4(o0.x, o1.x, o2.x, o3.x);
        ogp[q+h] = make_float4(o0.y, o1.y, o2.y, o3.y);
        obp[q+h] = make_float4(o0.z, o1.z, o2.z, o3.z);
    }
}

// ---------------- launch ------------------------------------------------------
extern "C" void kernel_launch(void* const* d_in, const int* in_sizes, int n_in,
                              void* d_out, int out_size) {
    const float* imgs   = (const float*)d_in[0];
    const float* w1 = (const float*)d_in[1];  const float* b1 = (const float*)d_in[2];
    const float* g1 = (const float*)d_in[3];  const float* be1 = (const float*)d_in[4];
    const float* w2 = (const float*)d_in[5];  const float* b2 = (const float*)d_in[6];
    const float* g2 = (const float*)d_in[7];  const float* be2 = (const float*)d_in[8];
    const float* w3 = (const float*)d_in[9];  const float* b3 = (const float*)d_in[10];
    const float* g3 = (const float*)d_in[11]; const float* be3 = (const float*)d_in[12];
    const float* w4 = (const float*)d_in[13]; const float* b4 = (const float*)d_in[14];
    const float* g4 = (const float*)d_in[15]; const float* be4 = (const float*)d_in[16];
    const float* w5 = (const float*)d_in[17]; const float* b5 = (const float*)d_in[18];
    const float* wgen_w = (const float*)d_in[19]; const float* wgen_b = (const float*)d_in[20];
    const float* basis_w = (const float*)d_in[21];
    const float* ada_w = (const float*)d_in[22]; const float* ada_b = (const float*)d_in[23];
    float* out = (float*)d_out;

    void *p_rs, *p_a1, *p_a2, *p_a3, *p_a4, *p_a5;
    cudaGetSymbolAddress(&p_rs, g_rs);
    cudaGetSymbolAddress(&p_a1, g_a1);
    cudaGetSymbolAddress(&p_a2, g_a2);
    cudaGetSymbolAddress(&p_a3, g_a3);
    cudaGetSymbolAddress(&p_a4, g_a4);
    cudaGetSymbolAddress(&p_a5, g_a5);

    const int T = 256;

    resize_k<<<(BATCH*3*256*256 + T-1)/T, T>>>(imgs);

    conv_k<3,  16, 256, 256><<<BATCH*16*(128*128/256), 256>>>((const float*)p_rs, w1, b1, (float*)p_a1);
    inorm_k<<<BATCH*16,  T>>>((float*)p_a1, g1, be1, 16, 128*128);
    conv_k<16, 32, 128, 256><<<BATCH*32*(64*64/256),   256>>>((const float*)p_a1, w2, b2, (float*)p_a2);
    inorm_k<<<BATCH*32,  T>>>((float*)p_a2, g2, be2, 32, 64*64);
    conv_k<32, 64, 64, 256><<<BATCH*64*(32*32/256),    256>>>((const float*)p_a2, w3, b3, (float*)p_a3);
    inorm_k<<<BATCH*64,  T>>>((float*)p_a3, g3, be3, 64, 32*32);
    conv_k<64, 128, 32, 256><<<BATCH*128*(16*16/256),  256>>>((const float*)p_a3, w4, b4, (float*)p_a4);
    inorm_k<<<BATCH*128, T>>>((float*)p_a4, g4, be4, 128, 16*16);
    conv_k<128,128, 16, 64><<<BATCH*128*(8*8/64),      64>>>((const float*)p_a4, w5, b5, (float*)p_a5);

    fc_k<<<BATCH, 512>>>(wgen_w, wgen_b, ada_w, ada_b);
    lut_k<<<(BATCH*V3 + T-1)/T, T>>>(basis_w);

    trans_k<<<BATCH*((NPIX/8)/256), 256>>>(imgs, out);
}